// round 6
// baseline (speedup 1.0000x reference)
#include <cuda_runtime.h>

//
// Morphological skeleton — merged erode+dilate, one smem pass per iteration,
// shuffle-based horizontal neighbor exchange, register re-associated skel sum.
//
// skel = sum_{j=0..K-1} x_j  -  sum_{j=1..K} dilate3(x_j),   x_{j+1} = erode3(x_j)
//
// Pass p (cur = x_p): one LDS.128 per row-block; left/right neighbors come
// from __shfl of adjacent lanes (column edges are register replicates; only
// lane 0/31 mid-row use a 1-lane scalar LDS). Vertical 3-ring in registers
// produces erode -> nxt and dilate -> acc. The x_p term of the skel sum is
// taken from the in-register center row, so no second buffer read exists.
//
// R5 fix vs R4: row reads are index-clamped to RW-1 again (R4's pointer-step
// fallback only stepped back one row; strips overshooting the region read
// past the smem allocation -> illegal address).
//

#define IMG    1024
#define NIMG   16
#define TILE   128
#define HALO   12
#define RW     152                 /* region valid width/height   */
#define RWP    164                 /* padded row stride: 164%32=4 avoids cross-strip bank aliasing */
#define NCOL   38                  /* float4 columns: exactly covers 152 */
#define NSTR   16
#define NT     (NCOL*NSTR)         /* 608 threads = 19 warps      */
#define RPS    10                  /* rows per strip              */
#define SMEMB  (2 * RW * RWP * 4)  /* 199424 bytes                */

__device__ float g_scratch[(size_t)NIMG * IMG * IMG];

__device__ __forceinline__ float min3f(float a, float b, float c) { return fminf(fminf(a, b), c); }
__device__ __forceinline__ float max3f(float a, float b, float c) { return fmaxf(fmaxf(a, b), c); }

// One row-block: LDS.128 + 2 shfl (+ rare 1-lane scalar LDS) -> h-min/h-max.
// doMn/doMx are block-uniform.
__device__ __forceinline__ void rowmm(const float* __restrict__ row, int xb, int lane, int c,
                                      float4& v, float4& mn, float4& mx,
                                      bool doMn, bool doMx)
{
    v = *(const float4*)(row + xb);
    float l = __shfl_up_sync(0xffffffffu, v.w, 1);
    float r = __shfl_down_sync(0xffffffffu, v.x, 1);
    if (c == 0)                l = v.x;            // region edge: replicate (min-safe,
    else if (lane == 0)        l = row[xb - 1];    //  never feeds interior dilate)
    if (c == NCOL - 1)         r = v.w;
    else if (lane == 31)       r = row[xb + 4];
    if (doMn) {
        mn.x = min3f(l,   v.x, v.y);
        mn.y = min3f(v.x, v.y, v.z);
        mn.z = min3f(v.y, v.z, v.w);
        mn.w = min3f(v.z, v.w, r);
    }
    if (doMx) {
        mx.x = max3f(l,   v.x, v.y);
        mx.y = max3f(v.x, v.y, v.z);
        mx.z = max3f(v.y, v.z, v.w);
        mx.w = max3f(v.z, v.w, r);
    }
}

__global__ void __launch_bounds__(NT, 1)
skel_merged_kernel(const float* __restrict__ xin,
                   float* __restrict__ xout,
                   float* __restrict__ skel,
                   int K, int accum, int writex)
{
    extern __shared__ float smem[];
    float* cur = smem;             // x_p
    float* nxt = smem + RW * RWP;  // receives x_{p+1}

    const int tid  = threadIdx.x;
    const int lane = tid & 31;
    const int bx = blockIdx.x, by = blockIdx.y, bz = blockIdx.z;
    const int gx0 = bx * TILE - HALO;
    const int gy0 = by * TILE - HALO;
    const float* img = xin + (size_t)bz * IMG * IMG;

    // ---- load region with replicate clamp ----
    for (int i = tid; i < RW * RW; i += NT) {
        int y = i / RW;
        int x = i - y * RW;
        int gy = min(max(gy0 + y, 0), IMG - 1);
        int gx = min(max(gx0 + x, 0), IMG - 1);
        cur[y * RWP + x] = img[(size_t)gy * IMG + gx];
    }
    __syncthreads();

    const bool topE   = (by == 0);
    const bool botE   = (by == (int)gridDim.y - 1);
    const bool leftE  = (bx == 0);
    const bool rightE = (bx == (int)gridDim.x - 1);
    const bool anyE   = topE || botE || leftE || rightE;

    const int c  = tid % NCOL;                   // float4 column 0..37
    const int s  = tid / NCOL;                   // strip 0..15
    const int xb = c * 4;                        // 0..148
    const bool dcol = (xb >= HALO) && (xb + 4 <= HALO + TILE);  // interior col block
    const int y0 = s * RPS;

    float4 acc[RPS];
#pragma unroll
    for (int k = 0; k < RPS; k++) acc[k] = make_float4(0.f, 0.f, 0.f, 0.f);

    for (int p = 0; p <= K; ++p) {
        const bool doE = (p < K);
        const bool doD = (p > 0);
        const int  m   = K - p;                         // erode validity margin
        const int  elo = doE ? (HALO - m) : HALO;
        const int  ehi = doE ? (HALO + TILE + m) : (HALO + TILE);

        // prime 3-row ring (vertical replicate clamp; min-safe, clamped rows
        // never reach interior dilate consumers)
        float4 av, amn, amx, bv, bmn, bmx;
        rowmm(cur + max(y0 - 1, 0) * RWP,      xb, lane, c, av, amn, amx, doE, doD);
        rowmm(cur + min(y0, RW - 1) * RWP,     xb, lane, c, bv, bmn, bmx, doE, doD);

#pragma unroll
        for (int k = 0; k < RPS; k++) {
            const int y = y0 + k;
            float4 cv, cmn, cmx;
            rowmm(cur + min(y + 1, RW - 1) * RWP, xb, lane, c,
                  cv, cmn, cmx, doE, doD);

            // skel terms at interior: += x_p (p<K), -= dilate(x_p) (p>0)
            if (dcol && y >= HALO && y < HALO + TILE) {
                if (doD) {
                    float dx_ = max3f(amx.x, bmx.x, cmx.x);
                    float dy_ = max3f(amx.y, bmx.y, cmx.y);
                    float dz_ = max3f(amx.z, bmx.z, cmx.z);
                    float dw_ = max3f(amx.w, bmx.w, cmx.w);
                    if (doE) {
                        acc[k].x += bv.x - dx_;
                        acc[k].y += bv.y - dy_;
                        acc[k].z += bv.z - dz_;
                        acc[k].w += bv.w - dw_;
                    } else {
                        acc[k].x -= dx_; acc[k].y -= dy_;
                        acc[k].z -= dz_; acc[k].w -= dw_;
                    }
                } else {
                    acc[k].x += bv.x; acc[k].y += bv.y;
                    acc[k].z += bv.z; acc[k].w += bv.w;
                }
            }
            // erode -> x_{p+1}
            if (doE && y >= elo && y < ehi) {
                float4 e;
                e.x = min3f(amn.x, bmn.x, cmn.x);
                e.y = min3f(amn.y, bmn.y, cmn.y);
                e.z = min3f(amn.z, bmn.z, cmn.z);
                e.w = min3f(amn.w, bmn.w, cmn.w);
                *(float4*)(nxt + y * RWP + xb) = e;
            }
            av = bv; amn = bmn; amx = bmx;
            bv = cv; bmn = cmn; bmx = cmx;
        }
        __syncthreads();

        // image-border ring fix-up on freshly eroded buffer (edge blocks only)
        if (doE && anyE) {
            if (tid < TILE + 2) {
                int o = HALO - 1 + tid;                    // 11..140
                int sx = o;
                if (leftE  && sx < HALO)             sx = HALO;
                if (rightE && sx > HALO + TILE - 1)  sx = HALO + TILE - 1;
                int sy = o;
                if (topE && sy < HALO)               sy = HALO;
                if (botE && sy > HALO + TILE - 1)    sy = HALO + TILE - 1;
                if (topE)   nxt[(HALO - 1) * RWP + o]      = nxt[HALO * RWP + sx];
                if (botE)   nxt[(HALO + TILE) * RWP + o]   = nxt[(HALO + TILE - 1) * RWP + sx];
                if (leftE)  nxt[o * RWP + (HALO - 1)]      = nxt[sy * RWP + HALO];
                if (rightE) nxt[o * RWP + (HALO + TILE)]   = nxt[sy * RWP + (HALO + TILE - 1)];
            }
            __syncthreads();
        }

        if (doE) { float* t = cur; cur = nxt; nxt = t; }
    }

    // ---- outputs ----
    if (dcol) {
        float* so = skel + (size_t)bz * IMG * IMG;
        float* xo = xout + (size_t)bz * IMG * IMG;
#pragma unroll
        for (int k = 0; k < RPS; k++) {
            const int y = y0 + k;
            if (y >= HALO && y < HALO + TILE) {
                const size_t off = (size_t)(by * TILE + (y - HALO)) * IMG
                                 + (size_t)(bx * TILE + (xb - HALO));
                if (writex)
                    *(float4*)(xo + off) = *(const float4*)(cur + y * RWP + xb);
                if (accum) {
                    float4 sv = *(const float4*)(so + off);
                    sv.x += acc[k].x; sv.y += acc[k].y;
                    sv.z += acc[k].z; sv.w += acc[k].w;
                    *(float4*)(so + off) = sv;
                } else {
                    *(float4*)(so + off) = acc[k];
                }
            }
        }
    }
}

extern "C" void kernel_launch(void* const* d_in, const int* in_sizes, int n_in,
                              void* d_out, int out_size)
{
    (void)in_sizes; (void)n_in; (void)out_size;
    const float* x = (const float*)d_in[0];
    float* skel = (float*)d_out;

    float* scratch = nullptr;
    cudaGetSymbolAddress((void**)&scratch, g_scratch);

    cudaFuncSetAttribute(skel_merged_kernel,
                         cudaFuncAttributeMaxDynamicSharedMemorySize, SMEMB);

    dim3 grid(IMG / TILE, IMG / TILE, NIMG);   // 8 x 8 x 16
    // iterations 0..10 (11 terms): init skel, write x_11 to scratch
    skel_merged_kernel<<<grid, NT, SMEMB>>>(x, scratch, skel, 11, 0, 1);
    // iterations 11..20 (10 terms): accumulate skel
    skel_merged_kernel<<<grid, NT, SMEMB>>>(scratch, scratch, skel, 10, 1, 0);
}

// round 7
// speedup vs baseline: 1.2373x; 1.2373x over previous
#include <cuda_runtime.h>

//
// Morphological skeleton — merged erode+dilate, one smem pass per iteration.
// Scalar-LDS neighbor loads (R3 style, proven fastest), re-associated sum:
//
//   skel = sum_{j=0..K-1} x_j  -  sum_{j=1..K} dilate3(x_j),  x_{j+1} = erode3(x_j)
//
// so the x_p term comes from the in-register center row and the cross-buffer
// read of x_{p-1} is eliminated. hmax is computed only by interior-column
// threads on passes with a dilate term; hmin only while erosions remain.
//

#define IMG    1024
#define NIMG   16
#define TILE   128
#define HALO   12
#define RW     152                 /* region valid width/height   */
#define RWP    164                 /* padded row stride: 164%32=4 avoids cross-strip bank aliasing */
#define NCOL   38                  /* float4 columns: exactly covers 152 */
#define NSTR   16
#define NT     (NCOL*NSTR)         /* 608 threads = 19 warps      */
#define RPS    10                  /* rows per strip              */
#define SMEMB  (2 * RW * RWP * 4)  /* 199424 bytes                */

__device__ float g_scratch[(size_t)NIMG * IMG * IMG];

__device__ __forceinline__ float min3f(float a, float b, float c) { return fminf(fminf(a, b), c); }
__device__ __forceinline__ float max3f(float a, float b, float c) { return fmaxf(fmaxf(a, b), c); }

// One row-block: 1x LDS.128 + 2x independent scalar LDS (no shuffles — the
// scalar loads overlap with the vector load; shfl serializes, measured 2x).
__device__ __forceinline__ void rowmm(const float* __restrict__ row, int xb,
                                      float4& v, float4& mn, float4& mx,
                                      bool doMn, bool doMx)
{
    v = *(const float4*)(row + xb);
    float l = (xb > 0)       ? row[xb - 1] : v.x;   // region-edge replicate (min-safe;
    float r = (xb + 4 < RW)  ? row[xb + 4] : v.w;   //  never feeds interior dilate)
    if (doMn) {
        mn.x = min3f(l,   v.x, v.y);
        mn.y = min3f(v.x, v.y, v.z);
        mn.z = min3f(v.y, v.z, v.w);
        mn.w = min3f(v.z, v.w, r);
    }
    if (doMx) {
        mx.x = max3f(l,   v.x, v.y);
        mx.y = max3f(v.x, v.y, v.z);
        mx.z = max3f(v.y, v.z, v.w);
        mx.w = max3f(v.z, v.w, r);
    }
}

__global__ void __launch_bounds__(NT, 1)
skel_merged_kernel(const float* __restrict__ xin,
                   float* __restrict__ xout,
                   float* __restrict__ skel,
                   int K, int accum, int writex)
{
    extern __shared__ float smem[];
    float* cur = smem;             // x_p
    float* nxt = smem + RW * RWP;  // receives x_{p+1}

    const int tid = threadIdx.x;
    const int bx = blockIdx.x, by = blockIdx.y, bz = blockIdx.z;
    const int gx0 = bx * TILE - HALO;
    const int gy0 = by * TILE - HALO;
    const float* img = xin + (size_t)bz * IMG * IMG;

    // ---- load region with replicate clamp ----
    for (int i = tid; i < RW * RW; i += NT) {
        int y = i / RW;
        int x = i - y * RW;
        int gy = min(max(gy0 + y, 0), IMG - 1);
        int gx = min(max(gx0 + x, 0), IMG - 1);
        cur[y * RWP + x] = img[(size_t)gy * IMG + gx];
    }
    __syncthreads();

    const bool topE   = (by == 0);
    const bool botE   = (by == (int)gridDim.y - 1);
    const bool leftE  = (bx == 0);
    const bool rightE = (bx == (int)gridDim.x - 1);
    const bool anyE   = topE || botE || leftE || rightE;

    const int c  = tid % NCOL;                   // float4 column 0..37
    const int s  = tid / NCOL;                   // strip 0..15
    const int xb = c * 4;                        // 0..148
    const bool dcol = (xb >= HALO) && (xb + 4 <= HALO + TILE);  // interior col block
    const int y0 = s * RPS;

    float4 acc[RPS];
#pragma unroll
    for (int k = 0; k < RPS; k++) acc[k] = make_float4(0.f, 0.f, 0.f, 0.f);

    for (int p = 0; p <= K; ++p) {
        const bool doE = (p < K);
        const bool doD = (p > 0);
        const bool doMx = doD && dcol;           // hmax consumed only here
        const int  m   = K - p;                  // erode validity margin
        const int  elo = doE ? (HALO - m) : HALO;
        const int  ehi = doE ? (HALO + TILE + m) : (HALO + TILE);

        if (doE || dcol) {
            // prime 3-row ring (vertical replicate clamp; min-safe, clamped
            // rows never reach interior dilate consumers)
            float4 av, amn, amx, bv, bmn, bmx;
            rowmm(cur + max(y0 - 1, 0) * RWP, xb, av, amn, amx, doE, doMx);
            rowmm(cur + y0 * RWP,             xb, bv, bmn, bmx, doE, doMx);

#pragma unroll
            for (int k = 0; k < RPS; k++) {
                const int y = y0 + k;
                float4 cv, cmn, cmx;
                rowmm(cur + min(y + 1, RW - 1) * RWP, xb, cv, cmn, cmx, doE, doMx);

                // skel terms at interior rows: += x_p (p<K), -= dilate(x_p) (p>0)
                if (dcol && y >= HALO && y < HALO + TILE) {
                    if (doMx) {
                        acc[k].x -= max3f(amx.x, bmx.x, cmx.x);
                        acc[k].y -= max3f(amx.y, bmx.y, cmx.y);
                        acc[k].z -= max3f(amx.z, bmx.z, cmx.z);
                        acc[k].w -= max3f(amx.w, bmx.w, cmx.w);
                    }
                    if (doE) {
                        acc[k].x += bv.x; acc[k].y += bv.y;
                        acc[k].z += bv.z; acc[k].w += bv.w;
                    }
                }
                // erode -> x_{p+1}
                if (doE && y >= elo && y < ehi) {
                    float4 e;
                    e.x = min3f(amn.x, bmn.x, cmn.x);
                    e.y = min3f(amn.y, bmn.y, cmn.y);
                    e.z = min3f(amn.z, bmn.z, cmn.z);
                    e.w = min3f(amn.w, bmn.w, cmn.w);
                    *(float4*)(nxt + y * RWP + xb) = e;
                }
                av = bv; amn = bmn; amx = bmx;
                bv = cv; bmn = cmn; bmx = cmx;
            }
        }
        __syncthreads();

        // image-border ring fix-up on freshly eroded buffer (edge blocks only)
        if (doE && anyE) {
            if (tid < TILE + 2) {
                int o = HALO - 1 + tid;                    // 11..140
                int sx = o;
                if (leftE  && sx < HALO)             sx = HALO;
                if (rightE && sx > HALO + TILE - 1)  sx = HALO + TILE - 1;
                int sy = o;
                if (topE && sy < HALO)               sy = HALO;
                if (botE && sy > HALO + TILE - 1)    sy = HALO + TILE - 1;
                if (topE)   nxt[(HALO - 1) * RWP + o]      = nxt[HALO * RWP + sx];
                if (botE)   nxt[(HALO + TILE) * RWP + o]   = nxt[(HALO + TILE - 1) * RWP + sx];
                if (leftE)  nxt[o * RWP + (HALO - 1)]      = nxt[sy * RWP + HALO];
                if (rightE) nxt[o * RWP + (HALO + TILE)]   = nxt[sy * RWP + (HALO + TILE - 1)];
            }
            __syncthreads();
        }

        if (doE) { float* t = cur; cur = nxt; nxt = t; }
    }

    // ---- outputs ----
    if (dcol) {
        float* so = skel + (size_t)bz * IMG * IMG;
        float* xo = xout + (size_t)bz * IMG * IMG;
#pragma unroll
        for (int k = 0; k < RPS; k++) {
            const int y = y0 + k;
            if (y >= HALO && y < HALO + TILE) {
                const size_t off = (size_t)(by * TILE + (y - HALO)) * IMG
                                 + (size_t)(bx * TILE + (xb - HALO));
                if (writex)
                    *(float4*)(xo + off) = *(const float4*)(cur + y * RWP + xb);
                if (accum) {
                    float4 sv = *(const float4*)(so + off);
                    sv.x += acc[k].x; sv.y += acc[k].y;
                    sv.z += acc[k].z; sv.w += acc[k].w;
                    *(float4*)(so + off) = sv;
                } else {
                    *(float4*)(so + off) = acc[k];
                }
            }
        }
    }
}

extern "C" void kernel_launch(void* const* d_in, const int* in_sizes, int n_in,
                              void* d_out, int out_size)
{
    (void)in_sizes; (void)n_in; (void)out_size;
    const float* x = (const float*)d_in[0];
    float* skel = (float*)d_out;

    float* scratch = nullptr;
    cudaGetSymbolAddress((void**)&scratch, g_scratch);

    cudaFuncSetAttribute(skel_merged_kernel,
                         cudaFuncAttributeMaxDynamicSharedMemorySize, SMEMB);

    dim3 grid(IMG / TILE, IMG / TILE, NIMG);   // 8 x 8 x 16
    // iterations 0..10 (11 terms): init skel, write x_11 to scratch
    skel_merged_kernel<<<grid, NT, SMEMB>>>(x, scratch, skel, 11, 0, 1);
    // iterations 11..20 (10 terms): accumulate skel
    skel_merged_kernel<<<grid, NT, SMEMB>>>(scratch, scratch, skel, 10, 1, 0);
}